// round 2
// baseline (speedup 1.0000x reference)
#include <cuda_runtime.h>
#include <cstdint>
#include <math.h>

// Problem sizes (fixed per reference)
#define BROWS 32768
#define ND1   1024
#define ND2   4096

// ---------------- scratch (device globals; no allocations allowed) ----------------
__device__ float g_At[(size_t)BROWS * ND1];   // tf32-rounded g1           (128 MB)
__device__ float g_Bt[(size_t)ND2 * ND1];     // tf32-rounded nW^T [n][k]  (16 MB)
__device__ float g_invnc[ND2];
__device__ float g_pm[4 * BROWS];
__device__ float g_ps[4 * BROWS];

static constexpr float LSE_SCALE = 14.426950408889634f;   // beta * log2(e), beta=10
static constexpr float OUT_SCALE = 0.069314718055994531f; // ln2 / beta

// ---------------- small helpers ----------------
__device__ __forceinline__ uint32_t smem_to_u32(const void* smem_ptr) {
    uint32_t addr;
    asm("{ .reg .u64 tmp; cvta.to.shared.u64 tmp, %1; cvt.u32.u64 %0, tmp; }"
        : "=r"(addr) : "l"(smem_ptr));
    return addr;
}

__device__ __forceinline__ float tf32_rna(float x) {
    uint32_t r;
    asm("cvt.rna.tf32.f32 %0, %1;" : "=r"(r) : "f"(x));
    return __uint_as_float(r);
}

__device__ __forceinline__ float ex2(float x) {
    float y;
    asm("ex2.approx.f32 %0, %1;" : "=f"(y) : "f"(x));
    return y;
}

__device__ __forceinline__ void cp_async16(uint32_t dst, const void* src) {
    asm volatile("cp.async.cg.shared.global [%0], [%1], 16;" :: "r"(dst), "l"(src));
}

__device__ __forceinline__ void mma_tf32(float* d, const uint32_t* a, const uint32_t* b) {
    asm volatile(
        "mma.sync.aligned.m16n8k8.row.col.f32.tf32.tf32.f32 "
        "{%0,%1,%2,%3}, {%4,%5,%6,%7}, {%8,%9}, {%0,%1,%2,%3};"
        : "+f"(d[0]), "+f"(d[1]), "+f"(d[2]), "+f"(d[3])
        : "r"(a[0]), "r"(a[1]), "r"(a[2]), "r"(a[3]), "r"(b[0]), "r"(b[1]));
}

// ---------------- GEMM constants ----------------
static constexpr int THREADS_G    = 256;
static constexpr int LDSS         = 36;                 // padded float stride (144 B, 16B-aligned)
static constexpr int STAGE_FLOATS = 2 * 128 * LDSS;     // A tile + B tile
static constexpr int NSTAGE       = 4;
static constexpr int RED_OFF      = NSTAGE * STAGE_FLOATS;
static constexpr int SMEM_FLOATS  = RED_OFF + 2 * 4 * 128;
static constexpr int SMEM_TOTAL   = SMEM_FLOATS * 4;    // 151552 B

// ---------------- kernel 1: inverse column norms of W ----------------
__global__ void colnorm_kernel(const float* __restrict__ W) {
    __shared__ float red[256];
    const int tid = threadIdx.x;
    const int col = blockIdx.x * 32 + (tid & 31);
    const int seg = tid >> 5;             // 8 row segments of 128
    float s = 0.f;
    const int i0 = seg * 128;
    #pragma unroll 4
    for (int i = i0; i < i0 + 128; i++) {
        float v = W[(size_t)i * ND2 + col];
        s += v * v;
    }
    red[tid] = s;
    __syncthreads();
    if (tid < 32) {
        float t = red[tid];
        #pragma unroll
        for (int k = 1; k < 8; k++) t += red[tid + k * 32];
        g_invnc[blockIdx.x * 32 + tid] = rsqrtf(t);
    }
}

// ---------------- kernel 2: W -> normalized, transposed [N,K] tf32 ----------------
__global__ void convertW_kernel(const float* __restrict__ W) {
    __shared__ float tile[32][33];
    const int n0 = blockIdx.x * 32;
    const int k0 = blockIdx.y * 32;
    const int tx = threadIdx.x;   // 32
    const int ty = threadIdx.y;   // 8
    #pragma unroll
    for (int r = ty; r < 32; r += 8)
        tile[r][tx] = W[(size_t)(k0 + r) * ND2 + n0 + tx];
    __syncthreads();
    #pragma unroll
    for (int r = ty; r < 32; r += 8) {
        const int n = n0 + r;
        const float v = tile[tx][r] * g_invnc[n];   // = nW[k0+tx][n]
        g_Bt[(size_t)n * ND1 + k0 + tx] = tf32_rna(v);
    }
}

// ---------------- kernel 3: g1 -> tf32-rounded copy ----------------
__global__ void convertA_kernel(const float* __restrict__ g1) {
    const size_t i = (size_t)blockIdx.x * blockDim.x + threadIdx.x;   // float4 index
    const float4 v = reinterpret_cast<const float4*>(g1)[i];
    float4 o;
    o.x = tf32_rna(v.x); o.y = tf32_rna(v.y);
    o.z = tf32_rna(v.z); o.w = tf32_rna(v.w);
    reinterpret_cast<float4*>(g_At)[i] = o;
}

// ---------------- kernel 4: pipelined tf32 GEMM + online LSE ----------------
__global__ void __launch_bounds__(THREADS_G, 1) gemm_lse_kernel() {
    extern __shared__ float smem[];
    const int tid  = threadIdx.x;
    const int wid  = tid >> 5;
    const int lane = tid & 31;
    const int g    = lane >> 2;
    const int tig  = lane & 3;
    const int mw   = wid & 1;      // 2 M-warps
    const int nw   = wid >> 1;     // 4 N-warps
    const int qx   = blockIdx.x;          // column quarter (1024 cols)
    const int row0 = blockIdx.y * 128;    // row block
    const uint32_t su = smem_to_u32(smem);
    float* redm = smem + RED_OFF;         // [4][128]
    float* reds = redm + 4 * 128;

    // cp.async tile-fill indexing: each thread fills 4 A rows-chunks + 4 B
    const int frow = tid >> 3;            // + i*32
    const int fcol = tid & 7;             // 16B chunk

    float mrun = -INFINITY, srun = 0.f;

    for (int nt = 0; nt < 8; nt++) {
        const int n0 = qx * 1024 + nt * 128;

        float d[4][4][4];
        #pragma unroll
        for (int mi = 0; mi < 4; mi++)
            #pragma unroll
            for (int ni = 0; ni < 4; ni++)
                #pragma unroll
                for (int r = 0; r < 4; r++) d[mi][ni][r] = 0.f;

        auto load_chunk = [&](int kc) {
            const int kg = kc * 32;
            const uint32_t sa = su + (uint32_t)(kc & 3) * (STAGE_FLOATS * 4);
            const uint32_t sb = sa + 128 * LDSS * 4;
            #pragma unroll
            for (int i = 0; i < 4; i++) {
                const int r = frow + i * 32;
                cp_async16(sa + (uint32_t)(r * LDSS + fcol * 4) * 4,
                           g_At + (size_t)(row0 + r) * ND1 + kg + fcol * 4);
            }
            #pragma unroll
            for (int i = 0; i < 4; i++) {
                const int r = frow + i * 32;
                cp_async16(sb + (uint32_t)(r * LDSS + fcol * 4) * 4,
                           g_Bt + (size_t)(n0 + r) * ND1 + kg + fcol * 4);
            }
        };

        // prologue: 3 stages in flight
        #pragma unroll
        for (int p = 0; p < 3; p++) {
            load_chunk(p);
            asm volatile("cp.async.commit_group;" ::: "memory");
        }

        for (int kc = 0; kc < 32; kc++) {
            asm volatile("cp.async.wait_group 2;" ::: "memory");
            __syncthreads();
            if (kc < 29) load_chunk(kc + 3);
            asm volatile("cp.async.commit_group;" ::: "memory");

            const float* As = smem + (kc & 3) * STAGE_FLOATS;
            const float* Bs = As + 128 * LDSS;
            #pragma unroll
            for (int ks = 0; ks < 4; ks++) {
                const int kb = ks * 8;
                uint32_t a[4][4], b[4][2];
                #pragma unroll
                for (int mi = 0; mi < 4; mi++) {
                    const float* Ar = As + (mw * 64 + mi * 16 + g) * LDSS + kb;
                    a[mi][0] = __float_as_uint(Ar[tig]);
                    a[mi][1] = __float_as_uint(Ar[8 * LDSS + tig]);
                    a[mi][2] = __float_as_uint(Ar[tig + 4]);
                    a[mi][3] = __float_as_uint(Ar[8 * LDSS + tig + 4]);
                }
                #pragma unroll
                for (int ni = 0; ni < 4; ni++) {
                    const float* Br = Bs + (nw * 32 + ni * 8 + g) * LDSS + kb;
                    b[ni][0] = __float_as_uint(Br[tig]);
                    b[ni][1] = __float_as_uint(Br[tig + 4]);
                }
                #pragma unroll
                for (int mi = 0; mi < 4; mi++)
                    #pragma unroll
                    for (int ni = 0; ni < 4; ni++)
                        mma_tf32(d[mi][ni], a[mi], b[ni]);
            }
        }

        // ---- online LSE epilogue over this 128-col tile ----
        #pragma unroll
        for (int mi = 0; mi < 4; mi++) {
            #pragma unroll
            for (int h = 0; h < 2; h++) {
                float v[8];
                float m = -INFINITY;
                #pragma unroll
                for (int ni = 0; ni < 4; ni++) {
                    v[ni * 2]     = d[mi][ni][h * 2]     * LSE_SCALE;
                    v[ni * 2 + 1] = d[mi][ni][h * 2 + 1] * LSE_SCALE;
                    m = fmaxf(m, fmaxf(v[ni * 2], v[ni * 2 + 1]));
                }
                float s = 0.f;
                #pragma unroll
                for (int j = 0; j < 8; j++) s += ex2(v[j] - m);
                // quad reduce (cols within warp tile)
                #pragma unroll
                for (int off = 1; off <= 2; off <<= 1) {
                    const float om = __shfl_xor_sync(0xffffffffu, m, off);
                    const float os = __shfl_xor_sync(0xffffffffu, s, off);
                    const float nm = fmaxf(m, om);
                    s = s * ex2(m - nm) + os * ex2(om - nm);
                    m = nm;
                }
                if (tig == 0) {
                    const int lr = mw * 64 + mi * 16 + h * 8 + g;
                    redm[nw * 128 + lr] = m;
                    reds[nw * 128 + lr] = s;
                }
            }
        }
        __syncthreads();
        if (tid < 128) {
            #pragma unroll
            for (int w = 0; w < 4; w++) {
                const float m = redm[w * 128 + tid];
                const float s = reds[w * 128 + tid];
                const float nm = fmaxf(mrun, m);
                srun = srun * ex2(mrun - nm) + s * ex2(m - nm);
                mrun = nm;
            }
        }
        __syncthreads();
    }

    if (tid < 128) {
        g_pm[qx * BROWS + row0 + tid] = mrun;
        g_ps[qx * BROWS + row0 + tid] = srun;
    }
}

// ---------------- kernel 5: combine 4 partial LSEs per row ----------------
__global__ void combine_kernel(float* __restrict__ out) {
    const int row = blockIdx.x * blockDim.x + threadIdx.x;
    const float m0 = g_pm[row];
    const float m1 = g_pm[BROWS + row];
    const float m2 = g_pm[2 * BROWS + row];
    const float m3 = g_pm[3 * BROWS + row];
    const float M = fmaxf(fmaxf(m0, m1), fmaxf(m2, m3));
    const float S = g_ps[row]             * ex2(m0 - M)
                  + g_ps[BROWS + row]     * ex2(m1 - M)
                  + g_ps[2 * BROWS + row] * ex2(m2 - M)
                  + g_ps[3 * BROWS + row] * ex2(m3 - M);
    out[row] = -(M + log2f(S)) * OUT_SCALE;
}

// ---------------- launch ----------------
extern "C" void kernel_launch(void* const* d_in, const int* in_sizes, int n_in,
                              void* d_out, int out_size) {
    const float* g1 = (const float*)d_in[0];
    const float* W  = (const float*)d_in[1];
    float* out = (float*)d_out;

    cudaFuncSetAttribute(gemm_lse_kernel,
                         cudaFuncAttributeMaxDynamicSharedMemorySize, SMEM_TOTAL);

    colnorm_kernel<<<ND2 / 32, 256>>>(W);
    convertW_kernel<<<dim3(ND2 / 32, ND1 / 32), dim3(32, 8)>>>(W);
    convertA_kernel<<<(BROWS * (ND1 / 4)) / 256, 256>>>(g1);
    gemm_lse_kernel<<<dim3(4, BROWS / 128), THREADS_G, SMEM_TOTAL>>>();
    combine_kernel<<<BROWS / 256, 256>>>(out);
}

// round 5
// speedup vs baseline: 1.1876x; 1.1876x over previous
#include <cuda_runtime.h>
#include <cstdint>
#include <math.h>

// Problem sizes (fixed per reference)
#define BROWS 32768
#define ND1   1024
#define ND2   4096

// ---------------- scratch (device globals; no allocations allowed) ----------------
// Fragment-major layouts:
//  g_At: [row/16][k/8] tiles of 128 floats, tile = lane-major float4
//        (lane = (r&7)*4 + (k&3); e0=(r<8,k<4) e1=(r>=8,k<4) e2=(r<8,k>=4) e3=(r>=8,k>=4))
//  g_Bt: [n/8][k/8] tiles of 64 floats, tile = lane-major float2
//        (lane = (n&7)*4 + (k&3); e0=k&7<4, e1=k&7>=4)
__device__ float g_At[(size_t)BROWS * ND1];   // tf32-rounded g1 (fragment-major)
__device__ float g_Bt[(size_t)ND2 * ND1];     // tf32-rounded nW^T (fragment-major)
__device__ float g_invnc[ND2];
__device__ float g_pm[4 * BROWS];
__device__ float g_ps[4 * BROWS];

static constexpr float LSE_SCALE = 14.426950408889634f;   // beta * log2(e), beta=10
static constexpr float OUT_SCALE = 0.069314718055994531f; // ln2 / beta

// ---------------- small helpers ----------------
__device__ __forceinline__ float tf32_rna(float x) {
    uint32_t r;
    asm("cvt.rna.tf32.f32 %0, %1;" : "=r"(r) : "f"(x));
    return __uint_as_float(r);
}

__device__ __forceinline__ float ex2(float x) {
    float y;
    asm("ex2.approx.f32 %0, %1;" : "=f"(y) : "f"(x));
    return y;
}

__device__ __forceinline__ uint32_t smem_to_u32(const void* smem_ptr) {
    uint32_t addr;
    asm("{ .reg .u64 tmp; cvta.to.shared.u64 tmp, %1; cvt.u32.u64 %0, tmp; }"
        : "=r"(addr) : "l"(smem_ptr));
    return addr;
}

__device__ __forceinline__ void cp_async16(uint32_t dst, const void* src) {
    asm volatile("cp.async.cg.shared.global [%0], [%1], 16;" :: "r"(dst), "l"(src));
}

__device__ __forceinline__ void mma_tf32(float* d, const uint32_t* a, const uint32_t* b) {
    asm volatile(
        "mma.sync.aligned.m16n8k8.row.col.f32.tf32.tf32.f32 "
        "{%0,%1,%2,%3}, {%4,%5,%6,%7}, {%8,%9}, {%0,%1,%2,%3};"
        : "+f"(d[0]), "+f"(d[1]), "+f"(d[2]), "+f"(d[3])
        : "r"(a[0]), "r"(a[1]), "r"(a[2]), "r"(a[3]), "r"(b[0]), "r"(b[1]));
}

// ---------------- GEMM constants ----------------
static constexpr int THREADS_G    = 256;
static constexpr int STAGE_FLOATS = 8192;               // A 4096 + B 4096 floats (32 KB)
static constexpr int NSTAGE       = 4;
static constexpr int RED_OFF      = NSTAGE * STAGE_FLOATS;   // 32768
static constexpr int SMEM_FLOATS  = RED_OFF + 2 * 4 * 128;
static constexpr int SMEM_TOTAL   = SMEM_FLOATS * 4;    // 135168 B

// ---------------- kernel 1: inverse column norms of W ----------------
__global__ void colnorm_kernel(const float* __restrict__ W) {
    __shared__ float red[256];
    const int tid = threadIdx.x;
    const int col = blockIdx.x * 32 + (tid & 31);
    const int seg = tid >> 5;             // 8 row segments of 128
    float s = 0.f;
    const int i0 = seg * 128;
    #pragma unroll 4
    for (int i = i0; i < i0 + 128; i++) {
        float v = W[(size_t)i * ND2 + col];
        s += v * v;
    }
    red[tid] = s;
    __syncthreads();
    if (tid < 32) {
        float t = red[tid];
        #pragma unroll
        for (int k = 1; k < 8; k++) t += red[tid + k * 32];
        g_invnc[blockIdx.x * 32 + tid] = rsqrtf(t);
    }
}

// ------- kernel 2: W -> normalized, transposed, fragment-major tf32 -------
__global__ void convertW_kernel(const float* __restrict__ W) {
    __shared__ float t[32 * 33];
    const int n0 = blockIdx.x * 32;
    const int k0 = blockIdx.y * 32;
    const int tx = threadIdx.x & 31;
    const int ty = threadIdx.x >> 5;      // 0..7
    #pragma unroll
    for (int r = ty; r < 32; r += 8)
        t[r * 33 + tx] = W[(size_t)(k0 + r) * ND2 + n0 + tx];   // t[k_l][n_l]
    __syncthreads();
    const int g = tx >> 2, tig = tx & 3;
    #pragma unroll
    for (int j = 0; j < 2; j++) {
        const int tt = ty + j * 8;        // 0..15 tiles (nb 0..3, kb 0..3)
        const int nb = tt & 3, kb = tt >> 2;
        const int n_l = nb * 8 + g;
        const float inv = g_invnc[n0 + n_l];
        float2 o;
        o.x = tf32_rna(t[(kb * 8 + tig) * 33 + n_l] * inv);
        o.y = tf32_rna(t[(kb * 8 + tig + 4) * 33 + n_l] * inv);
        *reinterpret_cast<float2*>(
            g_Bt + ((size_t)(n0 / 8 + nb) * (ND1 / 8) + k0 / 8 + kb) * 64 + tx * 2) = o;
    }
}

// ------- kernel 3: g1 -> tf32-rounded, fragment-major -------
__global__ void convertA_kernel(const float* __restrict__ g1) {
    __shared__ float t[16 * 132];
    const int tid = threadIdx.x;
    const int rb = blockIdx.x;            // row block of 16
    const int kb0 = blockIdx.y * 16;      // 16 k-blocks of 8 (128 cols)
    const int r = tid >> 5;               // 0..7
    const int c4 = tid & 31;
    #pragma unroll
    for (int i = 0; i < 2; i++) {
        const float4 v = *reinterpret_cast<const float4*>(
            g1 + (size_t)(rb * 16 + r + i * 8) * ND1 + kb0 * 8 + c4 * 4);
        float* dst = t + (r + i * 8) * 132 + c4 * 4;
        dst[0] = tf32_rna(v.x); dst[1] = tf32_rna(v.y);
        dst[2] = tf32_rna(v.z); dst[3] = tf32_rna(v.w);
    }
    __syncthreads();
    const int lane = tid & 31;
    const int g = lane >> 2, tig = lane & 3;
    #pragma unroll
    for (int j = 0; j < 2; j++) {
        const int kb = (tid >> 5) + j * 8;   // 0..15
        float4 o;
        o.x = t[g * 132 + kb * 8 + tig];
        o.y = t[(g + 8) * 132 + kb * 8 + tig];
        o.z = t[g * 132 + kb * 8 + tig + 4];
        o.w = t[(g + 8) * 132 + kb * 8 + tig + 4];
        *reinterpret_cast<float4*>(
            g_At + ((size_t)rb * (ND1 / 8) + kb0 + kb) * 128 + lane * 4) = o;
    }
}

// ---------------- kernel 4: pipelined tf32 GEMM + online LSE ----------------
__global__ void __launch_bounds__(THREADS_G, 1) gemm_lse_kernel() {
    extern __shared__ float smem[];
    const int tid  = threadIdx.x;
    const int wid  = tid >> 5;
    const int lane = tid & 31;
    const int g    = lane >> 2;
    const int tig  = lane & 3;
    const int mw   = wid & 1;      // 2 M-warps (64 rows each)
    const int nw   = wid >> 1;     // 4 N-warps (32 cols each)
    const int qx   = blockIdx.x;          // column quarter (1024 cols)
    const int row0 = blockIdx.y * 128;    // row block
    const uint32_t su = smem_to_u32(smem);
    float* redm = smem + RED_OFF;         // [4][128]
    float* reds = redm + 4 * 128;

    const int rb0 = row0 >> 4;            // global A row-block base

    float mrun = -INFINITY, srun = 0.f;

    for (int nt = 0; nt < 8; nt++) {
        const int n0 = qx * 1024 + nt * 128;
        const int nb0 = n0 >> 3;          // global B n-block base

        float d[4][4][4];
        #pragma unroll
        for (int mi = 0; mi < 4; mi++)
            #pragma unroll
            for (int ni = 0; ni < 4; ni++)
                #pragma unroll
                for (int r = 0; r < 4; r++) d[mi][ni][r] = 0.f;

        // identity block copies: A = 8 segs of 2KB, B = 16 segs of 1KB
        auto load_chunk = [&](int kc) {
            const uint32_t st = su + (uint32_t)(kc & 3) * (STAGE_FLOATS * 4);
            #pragma unroll
            for (int i = 0; i < 4; i++) {
                const int id = tid + i * 256;          // 0..1023
                const int arb = id >> 7, aoff = id & 127;
                cp_async16(st + (uint32_t)(arb * 2048 + aoff * 16),
                           g_At + ((size_t)(rb0 + arb) * (ND1 / 8) + kc * 4) * 128 + aoff * 4);
            }
            #pragma unroll
            for (int i = 0; i < 4; i++) {
                const int id = tid + i * 256;
                const int bnb = id >> 6, boff = id & 63;
                cp_async16(st + (uint32_t)(16384 + bnb * 1024 + boff * 16),
                           g_Bt + ((size_t)(nb0 + bnb) * (ND1 / 8) + kc * 4) * 64 + boff * 4);
            }
        };

        // prologue: 3 stages in flight
        #pragma unroll
        for (int p = 0; p < 3; p++) {
            load_chunk(p);
            asm volatile("cp.async.commit_group;" ::: "memory");
        }

        for (int kc = 0; kc < 32; kc++) {
            asm volatile("cp.async.wait_group 2;" ::: "memory");
            __syncthreads();
            if (kc < 29) load_chunk(kc + 3);
            asm volatile("cp.async.commit_group;" ::: "memory");

            const float* As = smem + (kc & 3) * STAGE_FLOATS;
            const float* Bs = As + 4096;
            #pragma unroll
            for (int ks = 0; ks < 4; ks++) {
                uint32_t a[4][4], b[4][2];
                #pragma unroll
                for (int mi = 0; mi < 4; mi++) {
                    const float4 v = *reinterpret_cast<const float4*>(
                        As + ((mw * 4 + mi) * 4 + ks) * 128 + lane * 4);
                    a[mi][0] = __float_as_uint(v.x);
                    a[mi][1] = __float_as_uint(v.y);
                    a[mi][2] = __float_as_uint(v.z);
                    a[mi][3] = __float_as_uint(v.w);
                }
                #pragma unroll
                for (int ni = 0; ni < 4; ni++) {
                    const float2 v = *reinterpret_cast<const float2*>(
                        Bs + ((nw * 4 + ni) * 4 + ks) * 64 + lane * 2);
                    b[ni][0] = __float_as_uint(v.x);
                    b[ni][1] = __float_as_uint(v.y);
                }
                #pragma unroll
                for (int mi = 0; mi < 4; mi++)
                    #pragma unroll
                    for (int ni = 0; ni < 4; ni++)
                        mma_tf32(d[mi][ni], a[mi], b[ni]);
            }
        }

        // ---- online LSE epilogue over this 128-col tile ----
        #pragma unroll
        for (int mi = 0; mi < 4; mi++) {
            #pragma unroll
            for (int h = 0; h < 2; h++) {
                float v[8];
                float m = -INFINITY;
                #pragma unroll
                for (int ni = 0; ni < 4; ni++) {
                    v[ni * 2]     = d[mi][ni][h * 2]     * LSE_SCALE;
                    v[ni * 2 + 1] = d[mi][ni][h * 2 + 1] * LSE_SCALE;
                    m = fmaxf(m, fmaxf(v[ni * 2], v[ni * 2 + 1]));
                }
                float s = 0.f;
                #pragma unroll
                for (int j = 0; j < 8; j++) s += ex2(v[j] - m);
                #pragma unroll
                for (int off = 1; off <= 2; off <<= 1) {
                    const float om = __shfl_xor_sync(0xffffffffu, m, off);
                    const float os = __shfl_xor_sync(0xffffffffu, s, off);
                    const float nm = fmaxf(m, om);
                    s = s * ex2(m - nm) + os * ex2(om - nm);
                    m = nm;
                }
                if (tig == 0) {
                    const int lr = mw * 64 + mi * 16 + h * 8 + g;
                    redm[nw * 128 + lr] = m;
                    reds[nw * 128 + lr] = s;
                }
            }
        }
        __syncthreads();
        if (tid < 128) {
            #pragma unroll
            for (int w = 0; w < 4; w++) {
                const float m = redm[w * 128 + tid];
                const float s = reds[w * 128 + tid];
                const float nm = fmaxf(mrun, m);
                srun = srun * ex2(mrun - nm) + s * ex2(m - nm);
                mrun = nm;
            }
        }
        __syncthreads();
    }

    if (tid < 128) {
        g_pm[qx * BROWS + row0 + tid] = mrun;
        g_ps[qx * BROWS + row0 + tid] = srun;
    }
}

// ---------------- kernel 5: combine 4 partial LSEs per row ----------------
__global__ void combine_kernel(float* __restrict__ out) {
    const int row = blockIdx.x * blockDim.x + threadIdx.x;
    const float m0 = g_pm[row];
    const float m1 = g_pm[BROWS + row];
    const float m2 = g_pm[2 * BROWS + row];
    const float m3 = g_pm[3 * BROWS + row];
    const float M = fmaxf(fmaxf(m0, m1), fmaxf(m2, m3));
    const float S = g_ps[row]             * ex2(m0 - M)
                  + g_ps[BROWS + row]     * ex2(m1 - M)
                  + g_ps[2 * BROWS + row] * ex2(m2 - M)
                  + g_ps[3 * BROWS + row] * ex2(m3 - M);
    out[row] = -(M + log2f(S)) * OUT_SCALE;
}

// ---------------- launch ----------------
extern "C" void kernel_launch(void* const* d_in, const int* in_sizes, int n_in,
                              void* d_out, int out_size) {
    const float* g1 = (const float*)d_in[0];
    const float* W  = (const float*)d_in[1];
    float* out = (float*)d_out;

    cudaFuncSetAttribute(gemm_lse_kernel,
                         cudaFuncAttributeMaxDynamicSharedMemorySize, SMEM_TOTAL);

    colnorm_kernel<<<ND2 / 32, 256>>>(W);
    convertW_kernel<<<dim3(ND2 / 32, ND1 / 32), dim3(256)>>>(W);
    convertA_kernel<<<dim3(BROWS / 16, ND1 / 128), 256>>>(g1);
    gemm_lse_kernel<<<dim3(4, BROWS / 128), THREADS_G, SMEM_TOTAL>>>();
    combine_kernel<<<BROWS / 256, 256>>>(out);
}

// round 6
// speedup vs baseline: 1.4573x; 1.2271x over previous
#include <cuda_runtime.h>
#include <cstdint>
#include <math.h>

// Problem sizes (fixed per reference)
#define BROWS 32768
#define ND1   1024
#define ND2   4096

// ---------------- scratch (device globals; no allocations allowed) ----------------
// Fragment-major layouts:
//  g_At: [row/16][k/8] tiles of 128 floats, tile = lane-major float4
//  g_Bt: [n/8][k/8] tiles of 64 floats, tile = lane-major float2
__device__ float g_At[(size_t)BROWS * ND1];   // tf32-rounded g1 (fragment-major)
__device__ float g_Bt[(size_t)ND2 * ND1];     // tf32-rounded nW^T (fragment-major)
__device__ float g_invnc[ND2];
__device__ float g_pm[4 * BROWS];
__device__ float g_ps[4 * BROWS];

static constexpr float LSE_SCALE = 14.426950408889634f;   // beta * log2(e), beta=10
static constexpr float OUT_SCALE = 0.069314718055994531f; // ln2 / beta

// ---------------- small helpers ----------------
__device__ __forceinline__ float tf32_rna(float x) {
    uint32_t r;
    asm("cvt.rna.tf32.f32 %0, %1;" : "=r"(r) : "f"(x));
    return __uint_as_float(r);
}

__device__ __forceinline__ float ex2(float x) {
    float y;
    asm("ex2.approx.f32 %0, %1;" : "=f"(y) : "f"(x));
    return y;
}

__device__ __forceinline__ uint32_t smem_to_u32(const void* smem_ptr) {
    uint32_t addr;
    asm("{ .reg .u64 tmp; cvta.to.shared.u64 tmp, %1; cvt.u32.u64 %0, tmp; }"
        : "=r"(addr) : "l"(smem_ptr));
    return addr;
}

__device__ __forceinline__ void cp_async16(uint32_t dst, const void* src) {
    asm volatile("cp.async.cg.shared.global [%0], [%1], 16;" :: "r"(dst), "l"(src));
}

__device__ __forceinline__ void mma_tf32(float* d, const uint32_t* a, const uint32_t* b) {
    asm volatile(
        "mma.sync.aligned.m16n8k8.row.col.f32.tf32.tf32.f32 "
        "{%0,%1,%2,%3}, {%4,%5,%6,%7}, {%8,%9}, {%0,%1,%2,%3};"
        : "+f"(d[0]), "+f"(d[1]), "+f"(d[2]), "+f"(d[3])
        : "r"(a[0]), "r"(a[1]), "r"(a[2]), "r"(a[3]), "r"(b[0]), "r"(b[1]));
}

// ---------------- GEMM constants ----------------
static constexpr int THREADS_G    = 256;
static constexpr int STAGE_FLOATS = 4096;               // A 2048 + B 2048 floats (16 KB)
static constexpr int NSTAGE       = 4;
static constexpr int NCHUNK       = 64;                 // 1024 / 16
static constexpr int RED_OFF      = NSTAGE * STAGE_FLOATS;   // 16384 floats
static constexpr int SMEM_FLOATS  = RED_OFF + 2 * 4 * 128;
static constexpr int SMEM_TOTAL   = SMEM_FLOATS * 4;    // 69632 B

// ---------------- kernel 1: inverse column norms of W ----------------
__global__ void colnorm_kernel(const float* __restrict__ W) {
    __shared__ float red[256];
    const int tid = threadIdx.x;
    const int col = blockIdx.x * 32 + (tid & 31);
    const int seg = tid >> 5;             // 8 row segments of 128
    float s = 0.f;
    const int i0 = seg * 128;
    #pragma unroll 4
    for (int i = i0; i < i0 + 128; i++) {
        float v = W[(size_t)i * ND2 + col];
        s += v * v;
    }
    red[tid] = s;
    __syncthreads();
    if (tid < 32) {
        float t = red[tid];
        #pragma unroll
        for (int k = 1; k < 8; k++) t += red[tid + k * 32];
        g_invnc[blockIdx.x * 32 + tid] = rsqrtf(t);
    }
}

// ------- kernel 2: W -> normalized, transposed, fragment-major tf32 -------
__global__ void convertW_kernel(const float* __restrict__ W) {
    __shared__ float t[32 * 33];
    const int n0 = blockIdx.x * 32;
    const int k0 = blockIdx.y * 32;
    const int tx = threadIdx.x & 31;
    const int ty = threadIdx.x >> 5;      // 0..7
    #pragma unroll
    for (int r = ty; r < 32; r += 8)
        t[r * 33 + tx] = W[(size_t)(k0 + r) * ND2 + n0 + tx];   // t[k_l][n_l]
    __syncthreads();
    const int g = tx >> 2, tig = tx & 3;
    #pragma unroll
    for (int j = 0; j < 2; j++) {
        const int tt = ty + j * 8;        // 0..15 tiles (nb 0..3, kb 0..3)
        const int nb = tt & 3, kb = tt >> 2;
        const int n_l = nb * 8 + g;
        const float inv = g_invnc[n0 + n_l];
        float2 o;
        o.x = tf32_rna(t[(kb * 8 + tig) * 33 + n_l] * inv);
        o.y = tf32_rna(t[(kb * 8 + tig + 4) * 33 + n_l] * inv);
        *reinterpret_cast<float2*>(
            g_Bt + ((size_t)(n0 / 8 + nb) * (ND1 / 8) + k0 / 8 + kb) * 64 + tx * 2) = o;
    }
}

// ------- kernel 3: g1 -> tf32-rounded, fragment-major -------
__global__ void convertA_kernel(const float* __restrict__ g1) {
    __shared__ float t[16 * 132];
    const int tid = threadIdx.x;
    const int rb = blockIdx.x;            // row block of 16
    const int kb0 = blockIdx.y * 16;      // 16 k-blocks of 8 (128 cols)
    const int r = tid >> 5;               // 0..7
    const int c4 = tid & 31;
    #pragma unroll
    for (int i = 0; i < 2; i++) {
        const float4 v = *reinterpret_cast<const float4*>(
            g1 + (size_t)(rb * 16 + r + i * 8) * ND1 + kb0 * 8 + c4 * 4);
        float* dst = t + (r + i * 8) * 132 + c4 * 4;
        dst[0] = tf32_rna(v.x); dst[1] = tf32_rna(v.y);
        dst[2] = tf32_rna(v.z); dst[3] = tf32_rna(v.w);
    }
    __syncthreads();
    const int lane = tid & 31;
    const int g = lane >> 2, tig = lane & 3;
    #pragma unroll
    for (int j = 0; j < 2; j++) {
        const int kb = (tid >> 5) + j * 8;   // 0..15
        float4 o;
        o.x = t[g * 132 + kb * 8 + tig];
        o.y = t[(g + 8) * 132 + kb * 8 + tig];
        o.z = t[g * 132 + kb * 8 + tig + 4];
        o.w = t[(g + 8) * 132 + kb * 8 + tig + 4];
        *reinterpret_cast<float4*>(
            g_At + ((size_t)rb * (ND1 / 8) + kb0 + kb) * 128 + lane * 4) = o;
    }
}

// ---------------- kernel 4: pipelined tf32 GEMM + online LSE ----------------
__global__ void __launch_bounds__(THREADS_G, 2) gemm_lse_kernel() {
    extern __shared__ float smem[];
    const int tid  = threadIdx.x;
    const int wid  = tid >> 5;
    const int lane = tid & 31;
    const int g    = lane >> 2;
    const int tig  = lane & 3;
    const int mw   = wid & 1;      // 2 M-warps (64 rows each)
    const int nw   = wid >> 1;     // 4 N-warps (32 cols each)
    const int qx   = blockIdx.x;          // column quarter (1024 cols)
    const int row0 = blockIdx.y * 128;    // row block
    const uint32_t su = smem_to_u32(smem);
    float* redm = smem + RED_OFF;         // [4][128]
    float* reds = redm + 4 * 128;

    const int rb0 = row0 >> 4;            // global A row-block base

    // ---- thread-constant fill indexing (hoisted out of the mainloop) ----
    // A: two 16B chunks/thread/kc; segment per 16-row block (256 floats/kc)
    const int aarb0 = tid >> 6,          aoff0 = tid & 63;
    const int aarb1 = (tid + 256) >> 6,  aoff1 = (tid + 256) & 63;
    // B: two 16B chunks/thread/kc; segment per 8-n block (128 floats/kc)
    const int bnb0t = tid >> 5,          boff0 = tid & 31;
    const int bnb1t = (tid + 256) >> 5,  boff1 = (tid + 256) & 31;
    // smem destination byte offsets within a stage
    const uint32_t sA0 = (uint32_t)(aarb0 * 256 + aoff0 * 4) * 4;
    const uint32_t sA1 = (uint32_t)(aarb1 * 256 + aoff1 * 4) * 4;
    const uint32_t sB0 = (uint32_t)(2048 + bnb0t * 128 + boff0 * 4) * 4;
    const uint32_t sB1 = (uint32_t)(2048 + bnb1t * 128 + boff1 * 4) * 4;
    // global A float offsets (constant across nt; advance 256/kc)
    const size_t gA0b = (size_t)(rb0 + aarb0) * 16384 + aoff0 * 4;
    const size_t gA1b = (size_t)(rb0 + aarb1) * 16384 + aoff1 * 4;

    // fragment base offsets (floats within a stage)
    const int aFrag = mw * 4 * 256 + lane * 4;    // + mi*256 + ks*128
    const int bFrag = 2048 + nw * 4 * 128 + lane * 2;  // + ni*128 + ks*64

    float mrun = -INFINITY, srun = 0.f;

    for (int nt = 0; nt < 8; nt++) {
        const int n0 = qx * 1024 + nt * 128;
        const int nb0 = n0 >> 3;          // global B n-block base
        // global B float offsets (advance 128/kc)
        size_t gB0 = (size_t)(nb0 + bnb0t) * 8192 + boff0 * 4;
        size_t gB1 = (size_t)(nb0 + bnb1t) * 8192 + boff1 * 4;
        size_t gA0 = gA0b, gA1 = gA1b;

        float d[4][4][4];
        #pragma unroll
        for (int mi = 0; mi < 4; mi++)
            #pragma unroll
            for (int ni = 0; ni < 4; ni++)
                #pragma unroll
                for (int r = 0; r < 4; r++) d[mi][ni][r] = 0.f;

        // prologue: 3 stages in flight
        #pragma unroll
        for (int p = 0; p < 3; p++) {
            const uint32_t st = su + (uint32_t)p * (STAGE_FLOATS * 4);
            cp_async16(st + sA0, g_At + gA0);
            cp_async16(st + sA1, g_At + gA1);
            cp_async16(st + sB0, g_Bt + gB0);
            cp_async16(st + sB1, g_Bt + gB1);
            asm volatile("cp.async.commit_group;" ::: "memory");
            gA0 += 256; gA1 += 256; gB0 += 128; gB1 += 128;
        }

        for (int kc = 0; kc < NCHUNK; kc++) {
            asm volatile("cp.async.wait_group 2;" ::: "memory");
            __syncthreads();
            if (kc < NCHUNK - 3) {
                const uint32_t st = su + (uint32_t)((kc + 3) & 3) * (STAGE_FLOATS * 4);
                cp_async16(st + sA0, g_At + gA0);
                cp_async16(st + sA1, g_At + gA1);
                cp_async16(st + sB0, g_Bt + gB0);
                cp_async16(st + sB1, g_Bt + gB1);
                gA0 += 256; gA1 += 256; gB0 += 128; gB1 += 128;
            }
            asm volatile("cp.async.commit_group;" ::: "memory");

            const float* As = smem + (kc & 3) * STAGE_FLOATS;
            #pragma unroll
            for (int ks = 0; ks < 2; ks++) {
                uint32_t a[4][4];
                #pragma unroll
                for (int mi = 0; mi < 4; mi++) {
                    const float4 v = *reinterpret_cast<const float4*>(
                        As + aFrag + mi * 256 + ks * 128);
                    a[mi][0] = __float_as_uint(v.x);
                    a[mi][1] = __float_as_uint(v.y);
                    a[mi][2] = __float_as_uint(v.z);
                    a[mi][3] = __float_as_uint(v.w);
                }
                #pragma unroll
                for (int ni = 0; ni < 4; ni++) {
                    uint32_t b[2];
                    const float2 v = *reinterpret_cast<const float2*>(
                        As + bFrag + ni * 128 + ks * 64);
                    b[0] = __float_as_uint(v.x);
                    b[1] = __float_as_uint(v.y);
                    #pragma unroll
                    for (int mi = 0; mi < 4; mi++)
                        mma_tf32(d[mi][ni], a[mi], b);
                }
            }
        }

        // ---- online LSE epilogue over this 128-col tile ----
        #pragma unroll
        for (int mi = 0; mi < 4; mi++) {
            #pragma unroll
            for (int h = 0; h < 2; h++) {
                float v[8];
                float m = -INFINITY;
                #pragma unroll
                for (int ni = 0; ni < 4; ni++) {
                    v[ni * 2]     = d[mi][ni][h * 2]     * LSE_SCALE;
                    v[ni * 2 + 1] = d[mi][ni][h * 2 + 1] * LSE_SCALE;
                    m = fmaxf(m, fmaxf(v[ni * 2], v[ni * 2 + 1]));
                }
                float s = 0.f;
                #pragma unroll
                for (int j = 0; j < 8; j++) s += ex2(v[j] - m);
                #pragma unroll
                for (int off = 1; off <= 2; off <<= 1) {
                    const float om = __shfl_xor_sync(0xffffffffu, m, off);
                    const float os = __shfl_xor_sync(0xffffffffu, s, off);
                    const float nm = fmaxf(m, om);
                    s = s * ex2(m - nm) + os * ex2(om - nm);
                    m = nm;
                }
                if (tig == 0) {
                    const int lr = mw * 64 + mi * 16 + h * 8 + g;
                    redm[nw * 128 + lr] = m;
                    reds[nw * 128 + lr] = s;
                }
            }
        }
        __syncthreads();
        if (tid < 128) {
            #pragma unroll
            for (int w = 0; w < 4; w++) {
                const float m = redm[w * 128 + tid];
                const float s = reds[w * 128 + tid];
                const float nm = fmaxf(mrun, m);
                srun = srun * ex2(mrun - nm) + s * ex2(m - nm);
                mrun = nm;
            }
        }
        __syncthreads();
    }

    if (tid < 128) {
        g_pm[qx * BROWS + row0 + tid] = mrun;
        g_ps[qx * BROWS + row0 + tid] = srun;
    }
}

// ---------------- kernel 5: combine 4 partial LSEs per row ----------------
__global__ void combine_kernel(float* __restrict__ out) {
    const int row = blockIdx.x * blockDim.x + threadIdx.x;
    const float m0 = g_pm[row];
    const float m1 = g_pm[BROWS + row];
    const float m2 = g_pm[2 * BROWS + row];
    const float m3 = g_pm[3 * BROWS + row];
    const float M = fmaxf(fmaxf(m0, m1), fmaxf(m2, m3));
    const float S = g_ps[row]             * ex2(m0 - M)
                  + g_ps[BROWS + row]     * ex2(m1 - M)
                  + g_ps[2 * BROWS + row] * ex2(m2 - M)
                  + g_ps[3 * BROWS + row] * ex2(m3 - M);
    out[row] = -(M + log2f(S)) * OUT_SCALE;
}

// ---------------- launch ----------------
extern "C" void kernel_launch(void* const* d_in, const int* in_sizes, int n_in,
                              void* d_out, int out_size) {
    const float* g1 = (const float*)d_in[0];
    const float* W  = (const float*)d_in[1];
    float* out = (float*)d_out;

    cudaFuncSetAttribute(gemm_lse_kernel,
                         cudaFuncAttributeMaxDynamicSharedMemorySize, SMEM_TOTAL);

    colnorm_kernel<<<ND2 / 32, 256>>>(W);
    convertW_kernel<<<dim3(ND2 / 32, ND1 / 32), dim3(256)>>>(W);
    convertA_kernel<<<dim3(BROWS / 16, ND1 / 128), 256>>>(g1);
    gemm_lse_kernel<<<dim3(4, BROWS / 128), THREADS_G, SMEM_TOTAL>>>();
    combine_kernel<<<BROWS / 256, 256>>>(out);
}

// round 7
// speedup vs baseline: 1.4950x; 1.0259x over previous
#include <cuda_runtime.h>
#include <cstdint>
#include <math.h>

// Problem sizes (fixed per reference)
#define BROWS 32768
#define ND1   1024
#define ND2   4096

// ---------------- scratch (device globals; no allocations allowed) ----------------
// Fragment-major layouts:
//  g_At: [row/16][k/8] tiles of 128 floats, tile = lane-major float4
//  g_Bt: [n/8][k/16] tiles of 128 floats, tile = lane-major float4
//        lane = (n&7)*4 + (k&3 of each half); float4 = {B[k=t], B[k=t+4], B[k=8+t], B[k=12+t]}
__device__ float g_At[(size_t)BROWS * ND1];   // tf32-rounded g1 (fragment-major)
__device__ float g_Bt[(size_t)ND2 * ND1];     // tf32-rounded nW^T (fragment-major)
__device__ float g_invnc[ND2];
__device__ float g_pm[4 * BROWS];
__device__ float g_ps[4 * BROWS];

static constexpr float LSE_SCALE = 14.426950408889634f;   // beta * log2(e), beta=10
static constexpr float OUT_SCALE = 0.069314718055994531f; // ln2 / beta

// ---------------- small helpers ----------------
__device__ __forceinline__ float tf32_rna(float x) {
    uint32_t r;
    asm("cvt.rna.tf32.f32 %0, %1;" : "=r"(r) : "f"(x));
    return __uint_as_float(r);
}

__device__ __forceinline__ float ex2(float x) {
    float y;
    asm("ex2.approx.f32 %0, %1;" : "=f"(y) : "f"(x));
    return y;
}

__device__ __forceinline__ uint32_t smem_to_u32(const void* smem_ptr) {
    uint32_t addr;
    asm("{ .reg .u64 tmp; cvta.to.shared.u64 tmp, %1; cvt.u32.u64 %0, tmp; }"
        : "=r"(addr) : "l"(smem_ptr));
    return addr;
}

__device__ __forceinline__ void cp_async16(uint32_t dst, const void* src) {
    asm volatile("cp.async.cg.shared.global [%0], [%1], 16;" :: "r"(dst), "l"(src));
}

__device__ __forceinline__ void mma_tf32(float* d, const uint32_t* a, const uint32_t* b) {
    asm volatile(
        "mma.sync.aligned.m16n8k8.row.col.f32.tf32.tf32.f32 "
        "{%0,%1,%2,%3}, {%4,%5,%6,%7}, {%8,%9}, {%0,%1,%2,%3};"
        : "+f"(d[0]), "+f"(d[1]), "+f"(d[2]), "+f"(d[3])
        : "r"(a[0]), "r"(a[1]), "r"(a[2]), "r"(a[3]), "r"(b[0]), "r"(b[1]));
}

// ---------------- GEMM constants ----------------
static constexpr int THREADS_G    = 256;
static constexpr int CHUNK_FLOATS = 4096;                 // A 2048 + B 2048 (16 KB, 16 k)
static constexpr int SLOT_FLOATS  = 2 * CHUNK_FLOATS;     // pair slot (32 KB)
static constexpr int NSLOT        = 3;
static constexpr int RED_OFF      = NSLOT * SLOT_FLOATS;  // 24576 floats
static constexpr int SMEM_TOTAL   = (RED_OFF + 2 * 4 * 128) * 4;   // 102400 B
static constexpr int NPAIR_TOTAL  = 256;                  // 8 nt * 32 pairs

// ---------------- kernel 1: inverse column norms of W ----------------
__global__ void colnorm_kernel(const float* __restrict__ W) {
    __shared__ float red[256];
    const int tid = threadIdx.x;
    const int col = blockIdx.x * 32 + (tid & 31);
    const int seg = tid >> 5;             // 8 row segments of 128
    float s = 0.f;
    const int i0 = seg * 128;
    #pragma unroll 4
    for (int i = i0; i < i0 + 128; i++) {
        float v = W[(size_t)i * ND2 + col];
        s += v * v;
    }
    red[tid] = s;
    __syncthreads();
    if (tid < 32) {
        float t = red[tid];
        #pragma unroll
        for (int k = 1; k < 8; k++) t += red[tid + k * 32];
        g_invnc[blockIdx.x * 32 + tid] = rsqrtf(t);
    }
}

// ------- kernel 2: W -> normalized, transposed, 16-k fragment-major tf32 -------
__global__ void convertW_kernel(const float* __restrict__ W) {
    __shared__ float t[32 * 33];
    const int n0 = blockIdx.x * 32;
    const int k0 = blockIdx.y * 32;
    const int tx = threadIdx.x & 31;
    const int ty = threadIdx.x >> 5;      // 0..7 -> tile (k16 = ty>>2, nb = ty&3)
    #pragma unroll
    for (int r = ty; r < 32; r += 8)
        t[r * 33 + tx] = W[(size_t)(k0 + r) * ND2 + n0 + tx];   // t[k_l][n_l]
    __syncthreads();
    const int g = tx >> 2, tig = tx & 3;
    const int k16 = ty >> 2, nb = ty & 3;
    const int n_l = nb * 8 + g;
    const float inv = g_invnc[n0 + n_l];
    const int kb = k16 * 16;
    float4 o;
    o.x = tf32_rna(t[(kb + tig)      * 33 + n_l] * inv);
    o.y = tf32_rna(t[(kb + tig + 4)  * 33 + n_l] * inv);
    o.z = tf32_rna(t[(kb + tig + 8)  * 33 + n_l] * inv);
    o.w = tf32_rna(t[(kb + tig + 12) * 33 + n_l] * inv);
    *reinterpret_cast<float4*>(
        g_Bt + ((size_t)(n0 / 8 + nb) * (ND1 / 16) + k0 / 16 + k16) * 128 + tx * 4) = o;
}

// ------- kernel 3: g1 -> tf32-rounded, fragment-major -------
__global__ void convertA_kernel(const float* __restrict__ g1) {
    __shared__ float t[16 * 132];
    const int tid = threadIdx.x;
    const int rb = blockIdx.x;            // row block of 16
    const int kb0 = blockIdx.y * 16;      // 16 k-blocks of 8 (128 cols)
    const int r = tid >> 5;               // 0..7
    const int c4 = tid & 31;
    #pragma unroll
    for (int i = 0; i < 2; i++) {
        const float4 v = *reinterpret_cast<const float4*>(
            g1 + (size_t)(rb * 16 + r + i * 8) * ND1 + kb0 * 8 + c4 * 4);
        float* dst = t + (r + i * 8) * 132 + c4 * 4;
        dst[0] = tf32_rna(v.x); dst[1] = tf32_rna(v.y);
        dst[2] = tf32_rna(v.z); dst[3] = tf32_rna(v.w);
    }
    __syncthreads();
    const int lane = tid & 31;
    const int g = lane >> 2, tig = lane & 3;
    #pragma unroll
    for (int j = 0; j < 2; j++) {
        const int kb = (tid >> 5) + j * 8;   // 0..15
        float4 o;
        o.x = t[g * 132 + kb * 8 + tig];
        o.y = t[(g + 8) * 132 + kb * 8 + tig];
        o.z = t[g * 132 + kb * 8 + tig + 4];
        o.w = t[(g + 8) * 132 + kb * 8 + tig + 4];
        *reinterpret_cast<float4*>(
            g_At + ((size_t)rb * (ND1 / 8) + kb0 + kb) * 128 + lane * 4) = o;
    }
}

// ---------------- kernel 4: pipelined tf32 GEMM + online LSE ----------------
__global__ void __launch_bounds__(THREADS_G, 2) gemm_lse_kernel() {
    extern __shared__ float smem[];
    const int tid  = threadIdx.x;
    const int wid  = tid >> 5;
    const int lane = tid & 31;
    const int g    = lane >> 2;
    const int tig  = lane & 3;
    const int mw   = wid & 1;      // 2 M-warps (64 rows each)
    const int nw   = wid >> 1;     // 4 N-warps (32 cols each)
    const int qx   = blockIdx.x;          // column quarter (1024 cols)
    const int row0 = blockIdx.y * 128;    // row block
    const uint32_t su = smem_to_u32(smem);
    float* redm = smem + RED_OFF;         // [4][128]
    float* reds = redm + 4 * 128;

    const int rb0 = row0 >> 4;            // global A row-block base

    // ---- fill indexing (thread-constant) ----
    const int aarb = tid >> 6, aoff = tid & 63;       // A: rb aarb / aarb+4
    const int bnb  = tid >> 5, boff = tid & 31;       // B: nb bnb / bnb+8
    const uint32_t dA0 = (uint32_t)(aarb * 256 + aoff * 4) * 4;
    const uint32_t dA1 = (uint32_t)((aarb + 4) * 256 + aoff * 4) * 4;
    const uint32_t dB0 = (uint32_t)(2048 + bnb * 128 + boff * 4) * 4;
    const uint32_t dB1 = (uint32_t)(2048 + (bnb + 8) * 128 + boff * 4) * 4;
    const float* gA0 = g_At + (size_t)(rb0 + aarb) * 16384 + aoff * 4;
    const float* gA1 = gA0 + (size_t)4 * 16384;
    const float* gB0 = g_Bt + (size_t)(qx * 128 + bnb) * 8192 + boff * 4;
    const float* gB1 = gB0 + (size_t)8 * 8192;

    // fragment base offsets (floats within a chunk)
    const int aFrag = mw * 1024 + lane * 4;        // + mi*256 + ks*128
    const int bFrag = 2048 + nw * 512 + lane * 4;  // + ni*128

    float d[4][4][4];
    #pragma unroll
    for (int mi = 0; mi < 4; mi++)
        #pragma unroll
        for (int ni = 0; ni < 4; ni++)
            #pragma unroll
            for (int r = 0; r < 4; r++) d[mi][ni][r] = 0.f;

    float mrun = -INFINITY, srun = 0.f;

    // fill one pair (2 chunks) for global pair fgp into slot
    auto fill = [&](int fgp, int slot) {
        const uint32_t kA = (uint32_t)(fgp & 31) << 9;                       // A float off
        const uint32_t kB = ((uint32_t)(fgp >> 5) << 17)
                          + ((uint32_t)(fgp & 31) << 8);                     // B float off
        const uint32_t st = su + (uint32_t)slot * (SLOT_FLOATS * 4);
        cp_async16(st + dA0, gA0 + kA);
        cp_async16(st + dA1, gA1 + kA);
        cp_async16(st + dB0, gB0 + kB);
        cp_async16(st + dB1, gB1 + kB);
        cp_async16(st + 16384 + dA0, gA0 + kA + 256);
        cp_async16(st + 16384 + dA1, gA1 + kA + 256);
        cp_async16(st + 16384 + dB0, gB0 + kB + 128);
        cp_async16(st + 16384 + dB1, gB1 + kB + 128);
    };

    fill(0, 0);
    asm volatile("cp.async.commit_group;" ::: "memory");
    fill(1, 1);
    asm volatile("cp.async.commit_group;" ::: "memory");

    int slot = 0, pslot = 2;
    for (int gp = 0; gp < NPAIR_TOTAL; gp++) {
        asm volatile("cp.async.wait_group 1;" ::: "memory");
        __syncthreads();
        if (gp < NPAIR_TOTAL - 2) fill(gp + 2, pslot);
        asm volatile("cp.async.commit_group;" ::: "memory");

        const float* S = smem + slot * SLOT_FLOATS;
        #pragma unroll
        for (int c = 0; c < 2; c++) {
            const float* C = S + c * CHUNK_FLOATS;
            uint32_t b[4][4];
            #pragma unroll
            for (int ni = 0; ni < 4; ni++) {
                const float4 v = *reinterpret_cast<const float4*>(C + bFrag + ni * 128);
                b[ni][0] = __float_as_uint(v.x);
                b[ni][1] = __float_as_uint(v.y);
                b[ni][2] = __float_as_uint(v.z);
                b[ni][3] = __float_as_uint(v.w);
            }
            #pragma unroll
            for (int ks = 0; ks < 2; ks++) {
                uint32_t a[4][4];
                #pragma unroll
                for (int mi = 0; mi < 4; mi++) {
                    const float4 v = *reinterpret_cast<const float4*>(
                        C + aFrag + mi * 256 + ks * 128);
                    a[mi][0] = __float_as_uint(v.x);
                    a[mi][1] = __float_as_uint(v.y);
                    a[mi][2] = __float_as_uint(v.z);
                    a[mi][3] = __float_as_uint(v.w);
                }
                #pragma unroll
                for (int ni = 0; ni < 4; ni++)
                    #pragma unroll
                    for (int mi = 0; mi < 4; mi++)
                        mma_tf32(d[mi][ni], a[mi], &b[ni][ks * 2]);
            }
        }
        slot  = (slot == 2)  ? 0 : slot + 1;
        pslot = (pslot == 2) ? 0 : pslot + 1;

        if ((gp & 31) == 31) {
            // ---- online LSE epilogue over this 128-col tile ----
            #pragma unroll
            for (int mi = 0; mi < 4; mi++) {
                #pragma unroll
                for (int h = 0; h < 2; h++) {
                    float v[8];
                    float m = -INFINITY;
                    #pragma unroll
                    for (int ni = 0; ni < 4; ni++) {
                        v[ni * 2]     = d[mi][ni][h * 2]     * LSE_SCALE;
                        v[ni * 2 + 1] = d[mi][ni][h * 2 + 1] * LSE_SCALE;
                        m = fmaxf(m, fmaxf(v[ni * 2], v[ni * 2 + 1]));
                    }
                    float s = 0.f;
                    #pragma unroll
                    for (int j = 0; j < 8; j++) s += ex2(v[j] - m);
                    #pragma unroll
                    for (int off = 1; off <= 2; off <<= 1) {
                        const float om = __shfl_xor_sync(0xffffffffu, m, off);
                        const float os = __shfl_xor_sync(0xffffffffu, s, off);
                        const float nm = fmaxf(m, om);
                        s = s * ex2(m - nm) + os * ex2(om - nm);
                        m = nm;
                    }
                    if (tig == 0) {
                        const int lr = mw * 64 + mi * 16 + h * 8 + g;
                        redm[nw * 128 + lr] = m;
                        reds[nw * 128 + lr] = s;
                    }
                }
            }
            __syncthreads();
            if (tid < 128) {
                #pragma unroll
                for (int w = 0; w < 4; w++) {
                    const float m = redm[w * 128 + tid];
                    const float s = reds[w * 128 + tid];
                    const float nm = fmaxf(mrun, m);
                    srun = srun * ex2(mrun - nm) + s * ex2(m - nm);
                    mrun = nm;
                }
            }
            __syncthreads();
            #pragma unroll
            for (int mi = 0; mi < 4; mi++)
                #pragma unroll
                for (int ni = 0; ni < 4; ni++)
                    #pragma unroll
                    for (int r = 0; r < 4; r++) d[mi][ni][r] = 0.f;
        }
    }

    if (tid < 128) {
        g_pm[qx * BROWS + row0 + tid] = mrun;
        g_ps[qx * BROWS + row0 + tid] = srun;
    }
}

// ---------------- kernel 5: combine 4 partial LSEs per row ----------------
__global__ void combine_kernel(float* __restrict__ out) {
    const int row = blockIdx.x * blockDim.x + threadIdx.x;
    const float m0 = g_pm[row];
    const float m1 = g_pm[BROWS + row];
    const float m2 = g_pm[2 * BROWS + row];
    const float m3 = g_pm[3 * BROWS + row];
    const float M = fmaxf(fmaxf(m0, m1), fmaxf(m2, m3));
    const float S = g_ps[row]             * ex2(m0 - M)
                  + g_ps[BROWS + row]     * ex2(m1 - M)
                  + g_ps[2 * BROWS + row] * ex2(m2 - M)
                  + g_ps[3 * BROWS + row] * ex2(m3 - M);
    out[row] = -(M + log2f(S)) * OUT_SCALE;
}

// ---------------- launch ----------------
extern "C" void kernel_launch(void* const* d_in, const int* in_sizes, int n_in,
                              void* d_out, int out_size) {
    const float* g1 = (const float*)d_in[0];
    const float* W  = (const float*)d_in[1];
    float* out = (float*)d_out;

    cudaFuncSetAttribute(gemm_lse_kernel,
                         cudaFuncAttributeMaxDynamicSharedMemorySize, SMEM_TOTAL);

    colnorm_kernel<<<ND2 / 32, 256>>>(W);
    convertW_kernel<<<dim3(ND2 / 32, ND1 / 32), dim3(256)>>>(W);
    convertA_kernel<<<dim3(BROWS / 16, ND1 / 128), 256>>>(g1);
    gemm_lse_kernel<<<dim3(4, BROWS / 128), THREADS_G, SMEM_TOTAL>>>();
    combine_kernel<<<BROWS / 256, 256>>>(out);
}

// round 8
// speedup vs baseline: 1.6487x; 1.1028x over previous
#include <cuda_runtime.h>
#include <cstdint>
#include <math.h>

// Problem sizes (fixed per reference)
#define BROWS 32768
#define ND1   1024
#define ND2   4096

// ---------------- scratch (device globals; no allocations allowed) ----------------
// Fragment-major layouts:
//  g_At: [row/16][k/8] tiles of 128 floats, tile = lane-major float4
//  g_Bt: [n/8][k/16] tiles of 128 floats, tile = lane-major float4
__device__ float g_At[(size_t)BROWS * ND1];   // tf32-rounded g1 (fragment-major)
__device__ float g_Bt[(size_t)ND2 * ND1];     // tf32-rounded nW^T (fragment-major)
__device__ float g_invnc[ND2];
__device__ float g_pm[4 * BROWS];
__device__ float g_ps[4 * BROWS];

static constexpr float LSE_SCALE = 14.426950408889634f;   // beta * log2(e), beta=10
static constexpr float OUT_SCALE = 0.069314718055994531f; // ln2 / beta

// ---------------- small helpers ----------------
__device__ __forceinline__ float tf32_rna(float x) {
    uint32_t r;
    asm("cvt.rna.tf32.f32 %0, %1;" : "=r"(r) : "f"(x));
    return __uint_as_float(r);
}

__device__ __forceinline__ float ex2(float x) {
    float y;
    asm("ex2.approx.f32 %0, %1;" : "=f"(y) : "f"(x));
    return y;
}

__device__ __forceinline__ uint32_t smem_to_u32(const void* smem_ptr) {
    uint32_t addr;
    asm("{ .reg .u64 tmp; cvta.to.shared.u64 tmp, %1; cvt.u32.u64 %0, tmp; }"
        : "=r"(addr) : "l"(smem_ptr));
    return addr;
}

__device__ __forceinline__ void cp_async16(uint32_t dst, const void* src) {
    asm volatile("cp.async.cg.shared.global [%0], [%1], 16;" :: "r"(dst), "l"(src));
}

__device__ __forceinline__ void mma_tf32(float* d, const uint32_t* a, const uint32_t* b) {
    asm volatile(
        "mma.sync.aligned.m16n8k8.row.col.f32.tf32.tf32.f32 "
        "{%0,%1,%2,%3}, {%4,%5,%6,%7}, {%8,%9}, {%0,%1,%2,%3};"
        : "+f"(d[0]), "+f"(d[1]), "+f"(d[2]), "+f"(d[3])
        : "r"(a[0]), "r"(a[1]), "r"(a[2]), "r"(a[3]), "r"(b[0]), "r"(b[1]));
}

#define MBAR_INIT(addr, cnt) \
    asm volatile("mbarrier.init.shared.b64 [%0], %1;" :: "r"(addr), "r"((uint32_t)(cnt)) : "memory")

#define MBAR_ARRIVE(addr) \
    asm volatile("{\n\t.reg .b64 t;\n\tmbarrier.arrive.shared.b64 t, [%0];\n\t}" \
                 :: "r"(addr) : "memory")

#define CPASYNC_MBAR_ARRIVE(addr) \
    asm volatile("cp.async.mbarrier.arrive.noinc.shared.b64 [%0];" :: "r"(addr) : "memory")

#define MBAR_WAIT_PAR(addr, par) do {                                        \
    asm volatile(                                                            \
        "{\n\t"                                                              \
        ".reg .pred P;\n\t"                                                  \
        "WAIT_%=:\n\t"                                                       \
        "mbarrier.try_wait.parity.shared.b64 P, [%0], %1;\n\t"               \
        "@!P bra WAIT_%=;\n\t"                                               \
        "}"                                                                  \
        :: "r"(addr), "r"((uint32_t)(par)) : "memory");                      \
} while (0)

// ---------------- GEMM constants ----------------
static constexpr int THREADS_G    = 256;
static constexpr int CHUNK_FLOATS = 4096;                 // A 2048 + B 2048 (16 KB, 16 k)
static constexpr int SLOT_FLOATS  = 2 * CHUNK_FLOATS;     // pair slot (32 KB)
static constexpr int NSLOT        = 3;
static constexpr int RED_OFF      = NSLOT * SLOT_FLOATS;  // 24576 floats
static constexpr int MB_OFF       = (RED_OFF + 2 * 4 * 128) * 4;   // byte offset 102400
static constexpr int SMEM_TOTAL   = MB_OFF + 64;          // 102464 B
static constexpr int NPAIR_TOTAL  = 256;                  // 8 nt * 32 pairs

// ---------------- kernel 1: inverse column norms of W ----------------
__global__ void colnorm_kernel(const float* __restrict__ W) {
    __shared__ float red[256];
    const int tid = threadIdx.x;
    const int col = blockIdx.x * 32 + (tid & 31);
    const int seg = tid >> 5;             // 8 row segments of 128
    float s = 0.f;
    const int i0 = seg * 128;
    #pragma unroll 4
    for (int i = i0; i < i0 + 128; i++) {
        float v = W[(size_t)i * ND2 + col];
        s += v * v;
    }
    red[tid] = s;
    __syncthreads();
    if (tid < 32) {
        float t = red[tid];
        #pragma unroll
        for (int k = 1; k < 8; k++) t += red[tid + k * 32];
        g_invnc[blockIdx.x * 32 + tid] = rsqrtf(t);
    }
}

// ------- kernel 2: W -> normalized, transposed, 16-k fragment-major tf32 -------
__global__ void convertW_kernel(const float* __restrict__ W) {
    __shared__ float t[32 * 33];
    const int n0 = blockIdx.x * 32;
    const int k0 = blockIdx.y * 32;
    const int tx = threadIdx.x & 31;
    const int ty = threadIdx.x >> 5;      // 0..7 -> tile (k16 = ty>>2, nb = ty&3)
    #pragma unroll
    for (int r = ty; r < 32; r += 8)
        t[r * 33 + tx] = W[(size_t)(k0 + r) * ND2 + n0 + tx];   // t[k_l][n_l]
    __syncthreads();
    const int g = tx >> 2, tig = tx & 3;
    const int k16 = ty >> 2, nb = ty & 3;
    const int n_l = nb * 8 + g;
    const float inv = g_invnc[n0 + n_l];
    const int kb = k16 * 16;
    float4 o;
    o.x = tf32_rna(t[(kb + tig)      * 33 + n_l] * inv);
    o.y = tf32_rna(t[(kb + tig + 4)  * 33 + n_l] * inv);
    o.z = tf32_rna(t[(kb + tig + 8)  * 33 + n_l] * inv);
    o.w = tf32_rna(t[(kb + tig + 12) * 33 + n_l] * inv);
    *reinterpret_cast<float4*>(
        g_Bt + ((size_t)(n0 / 8 + nb) * (ND1 / 16) + k0 / 16 + k16) * 128 + tx * 4) = o;
}

// ------- kernel 3: g1 -> tf32-rounded, fragment-major -------
__global__ void convertA_kernel(const float* __restrict__ g1) {
    __shared__ float t[16 * 132];
    const int tid = threadIdx.x;
    const int rb = blockIdx.x;            // row block of 16
    const int kb0 = blockIdx.y * 16;      // 16 k-blocks of 8 (128 cols)
    const int r = tid >> 5;               // 0..7
    const int c4 = tid & 31;
    #pragma unroll
    for (int i = 0; i < 2; i++) {
        const float4 v = *reinterpret_cast<const float4*>(
            g1 + (size_t)(rb * 16 + r + i * 8) * ND1 + kb0 * 8 + c4 * 4);
        float* dst = t + (r + i * 8) * 132 + c4 * 4;
        dst[0] = tf32_rna(v.x); dst[1] = tf32_rna(v.y);
        dst[2] = tf32_rna(v.z); dst[3] = tf32_rna(v.w);
    }
    __syncthreads();
    const int lane = tid & 31;
    const int g = lane >> 2, tig = lane & 3;
    #pragma unroll
    for (int j = 0; j < 2; j++) {
        const int kb = (tid >> 5) + j * 8;   // 0..15
        float4 o;
        o.x = t[g * 132 + kb * 8 + tig];
        o.y = t[(g + 8) * 132 + kb * 8 + tig];
        o.z = t[g * 132 + kb * 8 + tig + 4];
        o.w = t[(g + 8) * 132 + kb * 8 + tig + 4];
        *reinterpret_cast<float4*>(
            g_At + ((size_t)rb * (ND1 / 8) + kb0 + kb) * 128 + lane * 4) = o;
    }
}

// ---------------- kernel 4: mbarrier-pipelined tf32 GEMM + online LSE ----------------
__global__ void __launch_bounds__(THREADS_G, 2) gemm_lse_kernel() {
    extern __shared__ float smem[];
    const int tid  = threadIdx.x;
    const int wid  = tid >> 5;
    const int lane = tid & 31;
    const int g    = lane >> 2;
    const int tig  = lane & 3;
    const int mw   = wid & 1;      // 2 M-warps (64 rows each)
    const int nw   = wid >> 1;     // 4 N-warps (32 cols each)
    const int qx   = blockIdx.x;          // column quarter (1024 cols)
    const int row0 = blockIdx.y * 128;    // row block
    const uint32_t su = smem_to_u32(smem);
    float* redm = smem + RED_OFF;         // [4][128]
    float* reds = redm + 4 * 128;
    const uint32_t mbF = su + MB_OFF;          // full[0..2], 8 B each
    const uint32_t mbE = su + MB_OFF + 24;     // empty[0..2]

    const int rb0 = row0 >> 4;            // global A row-block base

    if (tid == 0) {
        #pragma unroll
        for (int s = 0; s < NSLOT; s++) {
            MBAR_INIT(mbF + s * 8, THREADS_G);
            MBAR_INIT(mbE + s * 8, THREADS_G);
        }
    }
    __syncthreads();

    // ---- fill indexing (thread-constant) ----
    const int aarb = tid >> 6, aoff = tid & 63;       // A: rb aarb / aarb+4
    const int bnb  = tid >> 5, boff = tid & 31;       // B: nb bnb / bnb+8
    const uint32_t dA0 = (uint32_t)(aarb * 256 + aoff * 4) * 4;
    const uint32_t dA1 = (uint32_t)((aarb + 4) * 256 + aoff * 4) * 4;
    const uint32_t dB0 = (uint32_t)(2048 + bnb * 128 + boff * 4) * 4;
    const uint32_t dB1 = (uint32_t)(2048 + (bnb + 8) * 128 + boff * 4) * 4;
    const float* gA0 = g_At + (size_t)(rb0 + aarb) * 16384 + aoff * 4;
    const float* gA1 = gA0 + (size_t)4 * 16384;
    const float* gB0 = g_Bt + (size_t)(qx * 128 + bnb) * 8192 + boff * 4;
    const float* gB1 = gB0 + (size_t)8 * 8192;

    // fragment base offsets (floats within a chunk)
    const int aFrag = mw * 1024 + lane * 4;        // + mi*256 + ks*128
    const int bFrag = 2048 + nw * 512 + lane * 4;  // + ni*128

    float d[4][4][4];
    #pragma unroll
    for (int mi = 0; mi < 4; mi++)
        #pragma unroll
        for (int ni = 0; ni < 4; ni++)
            #pragma unroll
            for (int r = 0; r < 4; r++) d[mi][ni][r] = 0.f;

    float mrun = -INFINITY, srun = 0.f;

    // fill one pair (2 chunks) for global pair fgp into slot; defer full-arrive
    auto fill = [&](int fgp, int slot) {
        const uint32_t kA = (uint32_t)(fgp & 31) << 9;                       // A float off
        const uint32_t kB = ((uint32_t)(fgp >> 5) << 17)
                          + ((uint32_t)(fgp & 31) << 8);                     // B float off
        const uint32_t st = su + (uint32_t)slot * (SLOT_FLOATS * 4);
        cp_async16(st + dA0, gA0 + kA);
        cp_async16(st + dA1, gA1 + kA);
        cp_async16(st + dB0, gB0 + kB);
        cp_async16(st + dB1, gB1 + kB);
        cp_async16(st + 16384 + dA0, gA0 + kA + 256);
        cp_async16(st + 16384 + dA1, gA1 + kA + 256);
        cp_async16(st + 16384 + dB0, gB0 + kB + 128);
        cp_async16(st + 16384 + dB1, gB1 + kB + 128);
        CPASYNC_MBAR_ARRIVE(mbF + slot * 8);
    };

    // prologue: fill all 3 slots
    #pragma unroll
    for (int p = 0; p < NSLOT; p++) fill(p, p);

    int cs = 0, cph = 0;
    for (int gp = 0; gp < NPAIR_TOTAL; gp++) {
        const uint32_t mf = mbF + cs * 8;
        const uint32_t me = mbE + cs * 8;
        MBAR_WAIT_PAR(mf, cph);

        const float* S = smem + cs * SLOT_FLOATS;
        #pragma unroll
        for (int c = 0; c < 2; c++) {
            const float* C = S + c * CHUNK_FLOATS;
            uint32_t b[4][4];
            #pragma unroll
            for (int ni = 0; ni < 4; ni++) {
                const float4 v = *reinterpret_cast<const float4*>(C + bFrag + ni * 128);
                b[ni][0] = __float_as_uint(v.x);
                b[ni][1] = __float_as_uint(v.y);
                b[ni][2] = __float_as_uint(v.z);
                b[ni][3] = __float_as_uint(v.w);
            }
            #pragma unroll
            for (int ks = 0; ks < 2; ks++) {
                uint32_t a[4][4];
                #pragma unroll
                for (int mi = 0; mi < 4; mi++) {
                    const float4 v = *reinterpret_cast<const float4*>(
                        C + aFrag + mi * 256 + ks * 128);
                    a[mi][0] = __float_as_uint(v.x);
                    a[mi][1] = __float_as_uint(v.y);
                    a[mi][2] = __float_as_uint(v.z);
                    a[mi][3] = __float_as_uint(v.w);
                }
                #pragma unroll
                for (int ni = 0; ni < 4; ni++)
                    #pragma unroll
                    for (int mi = 0; mi < 4; mi++)
                        mma_tf32(d[mi][ni], a[mi], &b[ni][ks * 2]);
            }
        }
        MBAR_ARRIVE(me);

        // refill this slot 3 pairs ahead once every thread has consumed it
        if (gp < NPAIR_TOTAL - NSLOT) {
            MBAR_WAIT_PAR(me, cph);
            fill(gp + NSLOT, cs);
        }

        if (++cs == NSLOT) { cs = 0; cph ^= 1; }

        if ((gp & 31) == 31) {
            // ---- online LSE epilogue over this 128-col tile ----
            #pragma unroll
            for (int mi = 0; mi < 4; mi++) {
                #pragma unroll
                for (int h = 0; h < 2; h++) {
                    float v[8];
                    float m = -INFINITY;
                    #pragma unroll
                    for (int ni = 0; ni < 4; ni++) {
                        v[ni * 2]     = d[mi][ni][h * 2]     * LSE_SCALE;
                        v[ni * 2 + 1] = d[mi][ni][h * 2 + 1] * LSE_SCALE;
                        m = fmaxf(m, fmaxf(v[ni * 2], v[ni * 2 + 1]));
                    }
                    float s = 0.f;
                    #pragma unroll
                    for (int j = 0; j < 8; j++) s += ex2(v[j] - m);
                    #pragma unroll
                    for (int off = 1; off <= 2; off <<= 1) {
                        const float om = __shfl_xor_sync(0xffffffffu, m, off);
                        const float os = __shfl_xor_sync(0xffffffffu, s, off);
                        const float nm = fmaxf(m, om);
                        s = s * ex2(m - nm) + os * ex2(om - nm);
                        m = nm;
                    }
                    if (tig == 0) {
                        const int lr = mw * 64 + mi * 16 + h * 8 + g;
                        redm[nw * 128 + lr] = m;
                        reds[nw * 128 + lr] = s;
                    }
                }
            }
            __syncthreads();
            if (tid < 128) {
                #pragma unroll
                for (int w = 0; w < 4; w++) {
                    const float m = redm[w * 128 + tid];
                    const float s = reds[w * 128 + tid];
                    const float nm = fmaxf(mrun, m);
                    srun = srun * ex2(mrun - nm) + s * ex2(m - nm);
                    mrun = nm;
                }
            }
            __syncthreads();
            #pragma unroll
            for (int mi = 0; mi < 4; mi++)
                #pragma unroll
                for (int ni = 0; ni < 4; ni++)
                    #pragma unroll
                    for (int r = 0; r < 4; r++) d[mi][ni][r] = 0.f;
        }
    }

    if (tid < 128) {
        g_pm[qx * BROWS + row0 + tid] = mrun;
        g_ps[qx * BROWS + row0 + tid] = srun;
    }
}

// ---------------- kernel 5: combine 4 partial LSEs per row ----------------
__global__ void combine_kernel(float* __restrict__ out) {
    const int row = blockIdx.x * blockDim.x + threadIdx.x;
    const float m0 = g_pm[row];
    const float m1 = g_pm[BROWS + row];
    const float m2 = g_pm[2 * BROWS + row];
    const float m3 = g_pm[3 * BROWS + row];
    const float M = fmaxf(fmaxf(m0, m1), fmaxf(m2, m3));
    const float S = g_ps[row]             * ex2(m0 - M)
                  + g_ps[BROWS + row]     * ex2(m1 - M)
                  + g_ps[2 * BROWS + row] * ex2(m2 - M)
                  + g_ps[3 * BROWS + row] * ex2(m3 - M);
    out[row] = -(M + log2f(S)) * OUT_SCALE;
}

// ---------------- launch ----------------
extern "C" void kernel_launch(void* const* d_in, const int* in_sizes, int n_in,
                              void* d_out, int out_size) {
    const float* g1 = (const float*)d_in[0];
    const float* W  = (const float*)d_in[1];
    float* out = (float*)d_out;

    cudaFuncSetAttribute(gemm_lse_kernel,
                         cudaFuncAttributeMaxDynamicSharedMemorySize, SMEM_TOTAL);

    colnorm_kernel<<<ND2 / 32, 256>>>(W);
    convertW_kernel<<<dim3(ND2 / 32, ND1 / 32), dim3(256)>>>(W);
    convertA_kernel<<<dim3(BROWS / 16, ND1 / 128), 256>>>(g1);
    gemm_lse_kernel<<<dim3(4, BROWS / 128), THREADS_G, SMEM_TOTAL>>>();
    combine_kernel<<<BROWS / 256, 256>>>(out);
}